// round 9
// baseline (speedup 1.0000x reference)
#include <cuda_runtime.h>
#include <cuda_fp16.h>
#include <cstdint>
#include <cstddef>

// ---------------------------------------------------------------------------
// out[32,28672] = (act[32,8192] @ weight[8192,28672] int8-valued) * scale[1,28672]
// R8 evidence: barrier-coupled smem pipeline stuck at 62% DRAM. This round:
// ZERO smem / ZERO barriers / ZERO cp.async in the GEMM.
//   - weights: per-lane LDG.b32 of exactly the fragment words, double-buffered
//     registers, 2-chunk lookahead (32KB/SM in flight; sectors 100% used)
//   - act: pre-swizzled into mma fragment order (uint4 per lane) by a staging
//     kernel; GEMM loads it as coalesced LDG.128 from L2
//   - warps fully independent: no sync from first load to epilogue
// Probes (f32-widened act? int32-widened weights?) as before.
// ---------------------------------------------------------------------------

#define MDIM 32
#define KDIM 8192
#define NDIM 28672

static constexpr int N_TILE  = 128;
static constexpr int K_CHUNK = 32;
static constexpr int CHUNKS  = KDIM / K_CHUNK;  // 256
static constexpr int THREADS = 256;
static constexpr int N_TILES = NDIM / N_TILE;   // 224

// ---------------- device state / staging (no allocations allowed) ----------
__device__ int    g_w_is_i8;
__device__ int    g_act_is_f32;
__device__ __half g_act_f16[MDIM * KDIM];            // 512 KB
__device__ float  g_scale[NDIM];                     // 112 KB
__device__ uint4  g_act_frag[CHUNKS * 4 * 32];       // [kt][ks][mt][lane], 512 KB

// ---------------- PTX helpers ------------------------------------------------
static __device__ __forceinline__ uint32_t ldg_b32(const void* p) {
    uint32_t v;
    asm volatile("ld.global.nc.b32 %0, [%1];" : "=r"(v) : "l"(p));
    return v;
}
static __device__ __forceinline__ uint32_t ldg_u8(const void* p) {
    uint32_t v;
    asm volatile("ld.global.nc.u8 %0, [%1];" : "=r"(v) : "l"(p));
    return v;
}
static __device__ __forceinline__ void ldg_v4(uint4& v, const void* p) {
    asm volatile("ld.global.nc.v4.b32 {%0,%1,%2,%3}, [%4];"
                 : "=r"(v.x), "=r"(v.y), "=r"(v.z), "=r"(v.w) : "l"(p));
}
static __device__ __forceinline__ void mma16816(float* c, const uint32_t* a,
                                                uint32_t b0, uint32_t b1) {
    asm volatile(
        "mma.sync.aligned.m16n8k16.row.col.f32.f16.f16.f32 "
        "{%0,%1,%2,%3}, {%4,%5,%6,%7}, {%8,%9}, {%0,%1,%2,%3};"
        : "+f"(c[0]), "+f"(c[1]), "+f"(c[2]), "+f"(c[3])
        : "r"(a[0]), "r"(a[1]), "r"(a[2]), "r"(a[3]), "r"(b0), "r"(b1));
}
static __device__ __forceinline__ uint32_t prmt(uint32_t a, uint32_t b, uint32_t sel) {
    uint32_t d;
    asm("prmt.b32 %0, %1, %2, %3;" : "=r"(d) : "r"(a), "r"(b), "r"(sel));
    return d;
}
static __device__ __forceinline__ uint32_t subf16x2(uint32_t a, uint32_t b) {
    uint32_t d;
    asm("sub.rn.f16x2 %0, %1, %2;" : "=r"(d) : "r"(a), "r"(b));
    return d;
}
// Two int32 weight words (value in low byte) -> packed f16x2 {w0, w1}. Exact.
static __device__ __forceinline__ uint32_t cvt2_i32(uint32_t v0, uint32_t v1) {
    const uint32_t m = prmt(v0, v1, 0x0040u) ^ 0x8080u;        // {b0(v0), b0(v1)} +128
    return subf16x2(prmt(m, 0x64646464u, 0x4140u), 0x64806480u);
}
// Two zero-extended s8 bytes -> packed f16x2. Exact.
static __device__ __forceinline__ uint32_t cvt2_i8(uint32_t v0, uint32_t v1) {
    const uint32_t h = 0x64006400u | (v0 ^ 0x80u) | ((v1 ^ 0x80u) << 16);
    return subf16x2(h, 0x64806480u);
}

// ---------------- dtype probes -----------------------------------------------
__global__ void probe_kernel(const uint32_t* __restrict__ act_raw,
                             const int* __restrict__ w) {
    if (threadIdx.x == 0) {
        int nz = 0;   // f16->f32 widening leaves low 13 mantissa bits zero
        for (int i = 0; i < 256; i++) nz += ((act_raw[i] & 0x1FFFu) != 0u);
        g_act_is_f32 = (nz < 8) ? 1 : 0;
        int oor = 0;  // int32-widened s8 stays in [-128,127]
        for (int i = 0; i < 256; i++) { const int v = w[i]; oor |= (v > 127) | (v < -128); }
        g_w_is_i8 = oor ? 1 : 0;
    }
}

// ---------------- act / scale staging ----------------------------------------
__global__ void __launch_bounds__(256) cvt_act_kernel(const void* __restrict__ act) {
    const int i = blockIdx.x * 256 + threadIdx.x;      // 65536 threads, 4 f16 each
    if (g_act_is_f32) {
        const float4 v = ((const float4*)act)[i];
        __half2* d = (__half2*)(g_act_f16 + i * 4);
        d[0] = __floats2half2_rn(v.x, v.y);
        d[1] = __floats2half2_rn(v.z, v.w);
    } else {
        ((uint2*)g_act_f16)[i] = ((const uint2*)act)[i];
    }
}
__global__ void __launch_bounds__(256) cvt_scale_kernel(const void* __restrict__ scale) {
    const int i = blockIdx.x * 256 + threadIdx.x;
    if (i < NDIM)
        g_scale[i] = g_act_is_f32 ? ((const float*)scale)[i]
                                  : __half2float(((const __half*)scale)[i]);
}
// Pre-swizzle act into m16n8k16 A-fragment order: one uint4 per (kt,ks,mt,lane).
__global__ void __launch_bounds__(256) frag_act_kernel() {
    const int i    = blockIdx.x * 256 + threadIdx.x;   // CHUNKS*2*2*32 = 65536
    const int lane = i & 31;
    const int mt   = (i >> 5) & 1;
    const int ks   = (i >> 6) & 1;
    const int kt   = i >> 7;
    const int row  = mt * 16 + (lane >> 2);
    const int k    = kt * K_CHUNK + ks * 16 + (lane & 3) * 2;
    const uint32_t* A = (const uint32_t*)g_act_f16;
    uint4 f;
    f.x = A[(row * KDIM + k) >> 1];           // a0: {A[m][k],   A[m][k+1]}
    f.y = A[((row + 8) * KDIM + k) >> 1];     // a1: rows +8
    f.z = A[(row * KDIM + k + 8) >> 1];       // a2: cols +8
    f.w = A[((row + 8) * KDIM + k + 8) >> 1]; // a3: both
    g_act_frag[i] = f;
}

// ---------------- main GEMM (no smem, no barriers) ---------------------------
template <int WI8>
static __device__ __forceinline__ void gemm_body(
    const char* __restrict__ wb, int n0, int warp, int lane, float c[2][2][4])
{
    const int gid = lane >> 2;                // n within n8
    const int tig = lane & 3;                 // k-pair selector
    const size_t ELT   = WI8 ? 1 : 4;
    const size_t WSTEP = (size_t)K_CHUNK * NDIM * ELT;
    const size_t NTOFF = 8 * ELT;             // nt stride (8 cols)
    const size_t R1 = (size_t)NDIM * ELT;     // +1 row
    const size_t R8 = (size_t)NDIM * 8 * ELT; // +8 rows
    const size_t R9 = R8 + R1;

    const char* p0 = wb + ((size_t)(2 * tig) * NDIM + n0 + warp * 16 + gid) * ELT;
    const char* p1 = p0 + (size_t)16 * NDIM * ELT;

    uint32_t wbuf0[16], wbuf1[16];
    uint4    abuf0[4], abuf1[4];

    auto load_w = [&](uint32_t (&wf)[16]) {
#pragma unroll
        for (int ks = 0; ks < 2; ks++) {
            const char* p = ks ? p1 : p0;
#pragma unroll
            for (int nt = 0; nt < 2; nt++) {
                const char* q = p + nt * NTOFF;
                const int j = ks * 8 + nt * 4;
                if (WI8) {
                    wf[j+0] = ldg_u8(q);       wf[j+1] = ldg_u8(q + R1);
                    wf[j+2] = ldg_u8(q + R8);  wf[j+3] = ldg_u8(q + R9);
                } else {
                    wf[j+0] = ldg_b32(q);      wf[j+1] = ldg_b32(q + R1);
                    wf[j+2] = ldg_b32(q + R8); wf[j+3] = ldg_b32(q + R9);
                }
            }
        }
        p0 += WSTEP; p1 += WSTEP;
    };

    const uint4* afp = g_act_frag + lane;
    auto load_a = [&](uint4 (&af)[4], int kt) {
#pragma unroll
        for (int j = 0; j < 4; j++)
            ldg_v4(af[j], afp + (size_t)kt * 128 + j * 32);
    };

    // prologue: chunks 0 and 1 in flight
    load_w(wbuf0); load_a(abuf0, 0);
    load_w(wbuf1); load_a(abuf1, 1);

    auto body = [&](uint32_t (&wf)[16], uint4 (&af)[4], int kt) {
        // convert current weights -> 8 B fragments
        uint32_t bf[2][2][2];
#pragma unroll
        for (int ks = 0; ks < 2; ks++)
#pragma unroll
            for (int nt = 0; nt < 2; nt++) {
                const int j = ks * 8 + nt * 4;
                bf[ks][nt][0] = WI8 ? cvt2_i8(wf[j+0], wf[j+1]) : cvt2_i32(wf[j+0], wf[j+1]);
                bf[ks][nt][1] = WI8 ? cvt2_i8(wf[j+2], wf[j+3]) : cvt2_i32(wf[j+2], wf[j+3]);
            }
        // prefetch weights for chunk kt+2 into the just-freed buffer
        if (kt + 2 < CHUNKS) load_w(wf);
        // MMA
#pragma unroll
        for (int ks = 0; ks < 2; ks++)
#pragma unroll
            for (int nt = 0; nt < 2; nt++) {
                mma16816(c[0][nt], (const uint32_t*)&af[ks * 2 + 0], bf[ks][nt][0], bf[ks][nt][1]);
                mma16816(c[1][nt], (const uint32_t*)&af[ks * 2 + 1], bf[ks][nt][0], bf[ks][nt][1]);
            }
        // prefetch act for chunk kt+2 (L2-resident)
        if (kt + 2 < CHUNKS) load_a(af, kt + 2);
    };

    for (int kt2 = 0; kt2 < CHUNKS / 2; kt2++) {
        body(wbuf0, abuf0, 2 * kt2);
        body(wbuf1, abuf1, 2 * kt2 + 1);
    }
}

__global__ void __launch_bounds__(THREADS, 2) gemm_kernel(
    const void* __restrict__ wgt, void* __restrict__ out)
{
    const int tid  = threadIdx.x;
    const int warp = tid >> 5;
    const int lane = tid & 31;
    const int n0   = blockIdx.x * N_TILE;

    float c[2][2][4] = {};
    if (g_w_is_i8) gemm_body<1>((const char*)wgt, n0, warp, lane, c);
    else           gemm_body<0>((const char*)wgt, n0, warp, lane, c);

    // ---- epilogue: scale, round through f16 (match reference), store ----
    const int out_is_f32 = g_act_is_f32;
    const int nq    = (lane & 3) * 2;
    const int nbase = n0 + warp * 16;
    const float2 s0 = *(const float2*)&g_scale[nbase + nq];
    const float2 s1 = *(const float2*)&g_scale[nbase + 8 + nq];
#pragma unroll
    for (int mt = 0; mt < 2; mt++) {
        const int m0 = mt * 16 + (lane >> 2);
#pragma unroll
        for (int nt = 0; nt < 2; nt++) {
            const float2 sc = nt ? s1 : s0;
            const int n = nbase + nt * 8 + nq;
            const __half2 h0 = __floats2half2_rn(c[mt][nt][0] * sc.x, c[mt][nt][1] * sc.y);
            const __half2 h1 = __floats2half2_rn(c[mt][nt][2] * sc.x, c[mt][nt][3] * sc.y);
            if (out_is_f32) {
                float* o = (float*)out;
                *(float2*)(o + (size_t)m0 * NDIM + n)       = __half22float2(h0);
                *(float2*)(o + (size_t)(m0 + 8) * NDIM + n) = __half22float2(h1);
            } else {
                __half* o = (__half*)out;
                *(__half2*)(o + (size_t)m0 * NDIM + n)       = h0;
                *(__half2*)(o + (size_t)(m0 + 8) * NDIM + n) = h1;
            }
        }
    }
}

// ---------------- host side --------------------------------------------------
extern "C" void kernel_launch(void* const* d_in, const int* in_sizes, int n_in,
                              void* d_out, int out_size)
{
    const void* act   = d_in[0];
    const void* wgt   = d_in[1];
    const void* scale = d_in[2];

    probe_kernel<<<1, 32>>>((const uint32_t*)act, (const int*)wgt);
    cvt_act_kernel<<<(MDIM * KDIM / 4) / 256, 256>>>(act);
    cvt_scale_kernel<<<(NDIM + 255) / 256, 256>>>(scale);
    frag_act_kernel<<<(CHUNKS * 4 * 32) / 256, 256>>>();

    gemm_kernel<<<N_TILES, THREADS>>>(wgt, d_out);
}

// round 11
// speedup vs baseline: 1.1747x; 1.1747x over previous
#include <cuda_runtime.h>
#include <cuda_fp16.h>
#include <cstdint>
#include <cstddef>

// ---------------------------------------------------------------------------
// out[32,28672] = (act[32,8192] @ weight[8192,28672] int8-valued) * scale[1,28672]
// R8: cp.async+smem, block-barrier-coupled -> 62% DRAM, 207us.
// R9: scalar LDG, no smem -> LSU-issue bound, 265us.
// R10: warp-private cp.async pipelines (no __syncthreads) -- FAILED on a
//      stage-slot index bug (refilled slot kt%STAGES instead of
//      (kt+STAGES-1)%STAGES; slot 3 never filled).
// R11: same design, slot index fixed.
// ---------------------------------------------------------------------------

#define MDIM 32
#define KDIM 8192
#define NDIM 28672

static constexpr int N_TILE  = 128;
static constexpr int K_CHUNK = 32;
static constexpr int CHUNKS  = KDIM / K_CHUNK;  // 256
static constexpr int THREADS = 256;
static constexpr int N_TILES = NDIM / N_TILE;   // 224
static constexpr int STAGES  = 4;

// Per-warp weight stage: 32 k-rows x 16 cols.
//  int32 path: 64B data/row, pitch 80B (20 words) => gather bank =
//    (40*tig + nl) mod 32 = (8*tig + nl) mod 32 -> all 32 lanes distinct.
//  i8 fallback: 16B data/row, pitch 32B.
static constexpr int WPITCH32   = 80;
static constexpr int WPITCH8    = 32;
static constexpr int WARP_STAGE = 32 * WPITCH32;                 // 2560 B
static constexpr int SMEM_TOTAL = STAGES * 8 * WARP_STAGE;       // 81920 B

// ---------------- device state / staging (no allocations allowed) ----------
__device__ int    g_w_is_i8;
__device__ int    g_act_is_f32;
__device__ __half g_act_f16[MDIM * KDIM];            // 512 KB
__device__ float  g_scale[NDIM];                     // 112 KB
__device__ uint4  g_act_frag[CHUNKS * 4 * 32];       // [kt][ks][mt][lane], 512 KB

// ---------------- PTX helpers ------------------------------------------------
static __device__ __forceinline__ uint32_t smem_u32(const void* p) {
    uint32_t a;
    asm("{ .reg .u64 t; cvta.to.shared.u64 t, %1; cvt.u32.u64 %0, t; }" : "=r"(a) : "l"(p));
    return a;
}
static __device__ __forceinline__ void cp16(uint32_t dst, const void* src) {
    asm volatile("cp.async.cg.shared.global [%0], [%1], 16;" :: "r"(dst), "l"(src) : "memory");
}
static __device__ __forceinline__ void cp_commit() {
    asm volatile("cp.async.commit_group;" ::: "memory");
}
template <int N>
static __device__ __forceinline__ void cp_wait() {
    asm volatile("cp.async.wait_group %0;" :: "n"(N) : "memory");
}
static __device__ __forceinline__ void ldg_v4(uint4& v, const void* p) {
    asm volatile("ld.global.nc.v4.b32 {%0,%1,%2,%3}, [%4];"
                 : "=r"(v.x), "=r"(v.y), "=r"(v.z), "=r"(v.w) : "l"(p));
}
static __device__ __forceinline__ uint32_t lds_b32(uint32_t addr) {
    uint32_t v;
    asm volatile("ld.shared.b32 %0, [%1];" : "=r"(v) : "r"(addr));
    return v;
}
static __device__ __forceinline__ uint32_t lds_u8(uint32_t addr) {
    uint32_t v;
    asm volatile("ld.shared.u8 %0, [%1];" : "=r"(v) : "r"(addr));
    return v;
}
static __device__ __forceinline__ void mma16816(float* c, const uint32_t* a,
                                                uint32_t b0, uint32_t b1) {
    asm volatile(
        "mma.sync.aligned.m16n8k16.row.col.f32.f16.f16.f32 "
        "{%0,%1,%2,%3}, {%4,%5,%6,%7}, {%8,%9}, {%0,%1,%2,%3};"
        : "+f"(c[0]), "+f"(c[1]), "+f"(c[2]), "+f"(c[3])
        : "r"(a[0]), "r"(a[1]), "r"(a[2]), "r"(a[3]), "r"(b0), "r"(b1));
}
static __device__ __forceinline__ uint32_t prmt(uint32_t a, uint32_t b, uint32_t sel) {
    uint32_t d;
    asm("prmt.b32 %0, %1, %2, %3;" : "=r"(d) : "r"(a), "r"(b), "r"(sel));
    return d;
}
static __device__ __forceinline__ uint32_t subf16x2(uint32_t a, uint32_t b) {
    uint32_t d;
    asm("sub.rn.f16x2 %0, %1, %2;" : "=r"(d) : "r"(a), "r"(b));
    return d;
}
// Two int32 words (s8 value in low byte) -> packed f16x2 {w0, w1}. Exact.
static __device__ __forceinline__ uint32_t cvt2_i32(uint32_t v0, uint32_t v1) {
    const uint32_t m = prmt(v0, v1, 0x0040u) ^ 0x8080u;
    return subf16x2(prmt(m, 0x64646464u, 0x4140u), 0x64806480u);
}
static __device__ __forceinline__ uint32_t cvt2_i8(uint32_t v0, uint32_t v1) {
    const uint32_t h = 0x64006400u | (v0 ^ 0x80u) | ((v1 ^ 0x80u) << 16);
    return subf16x2(h, 0x64806480u);
}

// ---------------- dtype probes -----------------------------------------------
__global__ void probe_kernel(const uint32_t* __restrict__ act_raw,
                             const int* __restrict__ w) {
    if (threadIdx.x == 0) {
        int nz = 0;   // f16->f32 widening leaves low 13 mantissa bits zero
        for (int i = 0; i < 256; i++) nz += ((act_raw[i] & 0x1FFFu) != 0u);
        g_act_is_f32 = (nz < 8) ? 1 : 0;
        int oor = 0;  // int32-widened s8 stays in [-128,127]
        for (int i = 0; i < 256; i++) { const int v = w[i]; oor |= (v > 127) | (v < -128); }
        g_w_is_i8 = oor ? 1 : 0;
    }
}

// ---------------- act / scale staging ----------------------------------------
__global__ void __launch_bounds__(256) cvt_act_kernel(const void* __restrict__ act) {
    const int i = blockIdx.x * 256 + threadIdx.x;      // 65536 threads, 4 f16 each
    if (g_act_is_f32) {
        const float4 v = ((const float4*)act)[i];
        __half2* d = (__half2*)(g_act_f16 + i * 4);
        d[0] = __floats2half2_rn(v.x, v.y);
        d[1] = __floats2half2_rn(v.z, v.w);
    } else {
        ((uint2*)g_act_f16)[i] = ((const uint2*)act)[i];
    }
}
__global__ void __launch_bounds__(256) cvt_scale_kernel(const void* __restrict__ scale) {
    const int i = blockIdx.x * 256 + threadIdx.x;
    if (i < NDIM)
        g_scale[i] = g_act_is_f32 ? ((const float*)scale)[i]
                                  : __half2float(((const __half*)scale)[i]);
}
// Pre-swizzle act into m16n8k16 A-fragment order (one uint4 per kt,ks,mt,lane).
__global__ void __launch_bounds__(256) frag_act_kernel() {
    const int i    = blockIdx.x * 256 + threadIdx.x;   // CHUNKS*2*2*32 = 65536
    const int lane = i & 31;
    const int mt   = (i >> 5) & 1;
    const int ks   = (i >> 6) & 1;
    const int kt   = i >> 7;
    const int row  = mt * 16 + (lane >> 2);
    const int k    = kt * K_CHUNK + ks * 16 + (lane & 3) * 2;
    const uint32_t* A = (const uint32_t*)g_act_f16;
    uint4 f;
    f.x = A[(row * KDIM + k) >> 1];
    f.y = A[((row + 8) * KDIM + k) >> 1];
    f.z = A[(row * KDIM + k + 8) >> 1];
    f.w = A[((row + 8) * KDIM + k + 8) >> 1];
    g_act_frag[i] = f;
}

// ---------------- warp-private stage fill ------------------------------------
template <int WI8>
static __device__ __forceinline__ void fill_stage(
    uint32_t wbase, const char* __restrict__ wsrc0, int kt, int s, int lane)
{
    const uint32_t dst = wbase + s * (8 * WARP_STAGE);
    if (WI8) {
        // 32 rows x 16B
        const char* src = wsrc0 + (size_t)kt * K_CHUNK * NDIM + (size_t)lane * NDIM;
        cp16(dst + lane * WPITCH8, src);
    } else {
        // 32 rows x 64B : 4 cp16 per lane
        const char* src = wsrc0 + ((size_t)kt * K_CHUNK * NDIM) * 4;
#pragma unroll
        for (int i = 0; i < 4; i++) {
            const int flat = i * 32 + lane;
            const int r = flat >> 2, c = flat & 3;
            cp16(dst + r * WPITCH32 + c * 16, src + ((size_t)r * NDIM) * 4 + c * 16);
        }
    }
    cp_commit();
}

// B fragment from warp-private smem.
template <int WI8>
static __device__ __forceinline__ uint32_t bfrag(uint32_t stage_base, int k, int nl) {
    if (WI8) {
        const uint32_t a0 = stage_base + (uint32_t)k * WPITCH8 + (uint32_t)nl;
        return cvt2_i8(lds_u8(a0), lds_u8(a0 + WPITCH8));
    } else {
        const uint32_t a0 = stage_base + (uint32_t)k * WPITCH32 + (uint32_t)nl * 4;
        return cvt2_i32(lds_b32(a0), lds_b32(a0 + WPITCH32));
    }
}

// ---------------- mainloop (no block barriers) -------------------------------
template <int WI8>
static __device__ __forceinline__ void gemm_body(
    const char* __restrict__ wb, int n0, int warp, int lane, float c[2][2][4])
{
    const int gid = lane >> 2;
    const int tig = lane & 3;
    const char* wsrc0 = wb + ((size_t)(n0 + warp * 16)) * (WI8 ? 1 : 4);
    extern __shared__ char smem[];
    const uint32_t wbase = smem_u32(smem) + warp * WARP_STAGE;

    const uint4* afp = g_act_frag + lane;
    uint4 abuf0[4], abuf1[4];
    auto load_a = [&](uint4 (&af)[4], int kt) {
#pragma unroll
        for (int j = 0; j < 4; j++)
            ldg_v4(af[j], afp + (size_t)kt * 128 + j * 32);
    };

    // prologue: weight stages for chunks 0..STAGES-2 + act chunks 0,1
#pragma unroll
    for (int p = 0; p < STAGES - 1; p++)
        fill_stage<WI8>(wbase, wsrc0, p, p, lane);
    load_a(abuf0, 0);
    load_a(abuf1, 1);

    for (int kt = 0; kt < CHUNKS; kt++) {
        const int s = kt % STAGES;
        const int rem = CHUNKS - 1 - kt;
        if (rem >= 2)      cp_wait<2>();
        else if (rem == 1) cp_wait<1>();
        else               cp_wait<0>();
        __syncwarp();

        const uint32_t sbase = wbase + s * (8 * WARP_STAGE);
        uint4 (&af)[4] = (kt & 1) ? abuf1 : abuf0;

        // gather + convert B fragments for this chunk
        uint32_t bf[2][2][2];
#pragma unroll
        for (int ks = 0; ks < 2; ks++)
#pragma unroll
            for (int nt = 0; nt < 2; nt++) {
                const int k  = ks * 16 + tig * 2;
                const int nl = nt * 8 + gid;
                bf[ks][nt][0] = bfrag<WI8>(sbase, k,     nl);
                bf[ks][nt][1] = bfrag<WI8>(sbase, k + 8, nl);
            }
        __syncwarp();
        // refill: chunk kt+STAGES-1 into ITS OWN slot (R10 bug: used s here)
        if (kt + STAGES - 1 < CHUNKS)
            fill_stage<WI8>(wbase, wsrc0, kt + STAGES - 1,
                            (kt + STAGES - 1) % STAGES, lane);
        // MMA
#pragma unroll
        for (int ks = 0; ks < 2; ks++)
#pragma unroll
            for (int nt = 0; nt < 2; nt++) {
                mma16816(c[0][nt], (const uint32_t*)&af[ks * 2 + 0], bf[ks][nt][0], bf[ks][nt][1]);
                mma16816(c[1][nt], (const uint32_t*)&af[ks * 2 + 1], bf[ks][nt][0], bf[ks][nt][1]);
            }
        // prefetch act fragments for kt+2 (L2-resident)
        if (kt + 2 < CHUNKS) load_a(af, kt + 2);
    }
}

__global__ void __launch_bounds__(THREADS, 2) gemm_kernel(
    const void* __restrict__ wgt, void* __restrict__ out)
{
    const int tid  = threadIdx.x;
    const int warp = tid >> 5;
    const int lane = tid & 31;
    const int n0   = blockIdx.x * N_TILE;

    float c[2][2][4] = {};
    if (g_w_is_i8) gemm_body<1>((const char*)wgt, n0, warp, lane, c);
    else           gemm_body<0>((const char*)wgt, n0, warp, lane, c);

    // ---- epilogue: scale, round through f16 (match reference), store ----
    const int out_is_f32 = g_act_is_f32;
    const int nq    = (lane & 3) * 2;
    const int nbase = n0 + warp * 16;
    const float2 s0 = *(const float2*)&g_scale[nbase + nq];
    const float2 s1 = *(const float2*)&g_scale[nbase + 8 + nq];
#pragma unroll
    for (int mt = 0; mt < 2; mt++) {
        const int m0 = mt * 16 + (lane >> 2);
#pragma unroll
        for (int nt = 0; nt < 2; nt++) {
            const float2 sc = nt ? s1 : s0;
            const int n = nbase + nt * 8 + nq;
            const __half2 h0 = __floats2half2_rn(c[mt][nt][0] * sc.x, c[mt][nt][1] * sc.y);
            const __half2 h1 = __floats2half2_rn(c[mt][nt][2] * sc.x, c[mt][nt][3] * sc.y);
            if (out_is_f32) {
                float* o = (float*)out;
                *(float2*)(o + (size_t)m0 * NDIM + n)       = __half22float2(h0);
                *(float2*)(o + (size_t)(m0 + 8) * NDIM + n) = __half22float2(h1);
            } else {
                __half* o = (__half*)out;
                *(__half2*)(o + (size_t)m0 * NDIM + n)       = h0;
                *(__half2*)(o + (size_t)(m0 + 8) * NDIM + n) = h1;
            }
        }
    }
}

// ---------------- host side --------------------------------------------------
extern "C" void kernel_launch(void* const* d_in, const int* in_sizes, int n_in,
                              void* d_out, int out_size)
{
    const void* act   = d_in[0];
    const void* wgt   = d_in[1];
    const void* scale = d_in[2];

    probe_kernel<<<1, 32>>>((const uint32_t*)act, (const int*)wgt);
    cvt_act_kernel<<<(MDIM * KDIM / 4) / 256, 256>>>(act);
    cvt_scale_kernel<<<(NDIM + 255) / 256, 256>>>(scale);
    frag_act_kernel<<<(CHUNKS * 4 * 32) / 256, 256>>>();

    cudaFuncSetAttribute(gemm_kernel, cudaFuncAttributeMaxDynamicSharedMemorySize, SMEM_TOTAL);
    gemm_kernel<<<N_TILES, THREADS, SMEM_TOTAL>>>(wgt, d_out);
}